// round 14
// baseline (speedup 1.0000x reference)
#include <cuda_runtime.h>
#include <cuda_bf16.h>
#include <cstdint>

// x:       (L=2048, B=16) int32   -> x[l*16 + b]
// embed_w: (V=50257, D=1024) fp32 -> w[t*1024 + d]
// out:     (B=16, D=1024, L=2048) fp32 -> out[b*D*L + d*L + l]
// rows with token >= 20 are zero; output scaled by sqrt(8).

#define L_DIM   2048
#define B_DIM   16
#define D_DIM   1024
#define MAXTOK  20
#define SCALE   2.8284271247461903f  // sqrt(8)

#define NBLK        4096
#define TPB         256
#define CHUNK_B     32768           // bytes of output per block (contiguous)
#define ZB_BYTES    16384           // smem zero-source buffer
// chunk floats = 8192 = one b, 4 consecutive d, all 2048 l

// Bit g (of 512): any token < MAXTOK for l in [4g,4g+4), any b. 16 words.
__device__ unsigned g_mask[16];

// ---------------------------------------------------------------------------
// Kernel 1: build 512-bit mask. 16 blocks x 1 warp, coalesced int4 reads.
// (byte-identical to R6's validated version)
// ---------------------------------------------------------------------------
__global__ void __launch_bounds__(32) mask_kernel(const int* __restrict__ x)
{
    const int wi   = blockIdx.x;
    const int lane = threadIdx.x;
    const int4* src = (const int4*)x + wi * 512;

    unsigned word = 0;
    #pragma unroll
    for (int j = 0; j < 16; j++) {
        int4 v = __ldg(src + j * 32 + lane);
        int hit = (v.x < MAXTOK) | (v.y < MAXTOK) |
                  (v.z < MAXTOK) | (v.w < MAXTOK);
        unsigned bal = __ballot_sync(0xFFFFFFFFu, hit);
        word |= ((bal & 0xFFFFu) ? 1u : 0u) << (2 * j);
        word |= ((bal >> 16)     ? 1u : 0u) << (2 * j + 1);
    }
    if (lane == 0) g_mask[wi] = word;
}

// ---------------------------------------------------------------------------
// Kernel 2: TMA bulk zero-fill + per-chunk fixup.
// STG fill was pinned at ~7 TB/s (SM-side store path). cp.async.bulk S2G
// goes through the async proxy straight to LTS (~6300 B/cyc chip cap,
// path-independent per B300_MICROARCH) — bypassing the L1tex STG limiter.
// Each block: zero 16KB smem once, two 16KB bulk copies to its contiguous
// 32KB output chunk, wait, then fix up rare rows WITHIN ITS OWN CHUNK.
// ---------------------------------------------------------------------------
__global__ void __launch_bounds__(TPB) tma_fill_kernel(
    const int* __restrict__ x,
    const float* __restrict__ w,
    float* __restrict__ out)
{
    __shared__ __align__(16) float4 zbuf[ZB_BYTES / 16];   // 16 KB zeros
    __shared__ unsigned s_mask[16];

    const int tid = threadIdx.x;
    const int bid = blockIdx.x;

    // 1) zero the smem source (4 float4 per thread)
    const float4 z = make_float4(0.f, 0.f, 0.f, 0.f);
    #pragma unroll
    for (int k = 0; k < ZB_BYTES / 16 / TPB; k++)
        zbuf[k * TPB + tid] = z;

    // order generic smem writes before async-proxy reads
    asm volatile("fence.proxy.async;" ::: "memory");
    __syncthreads();

    // 2) issue bulk zero-stores for this block's contiguous 32KB chunk
    char* gdst = (char*)out + (size_t)bid * CHUNK_B;
    if (tid == 0) {
        uint32_t saddr;
        asm("{ .reg .u64 t; cvta.to.shared.u64 t, %1; cvt.u32.u64 %0, t; }"
            : "=r"(saddr) : "l"((const void*)zbuf));
        asm volatile(
            "cp.async.bulk.global.shared::cta.bulk_group [%0], [%1], %2;"
            :: "l"(gdst), "r"(saddr), "r"((unsigned)ZB_BYTES) : "memory");
        asm volatile(
            "cp.async.bulk.global.shared::cta.bulk_group [%0], [%1], %2;"
            :: "l"(gdst + ZB_BYTES), "r"(saddr), "r"((unsigned)ZB_BYTES) : "memory");
        asm volatile("cp.async.bulk.commit_group;" ::: "memory");
    }

    // 3) stage the mask while TMA is in flight (64B, L2-hot)
    if (tid < 16) s_mask[tid] = g_mask[tid];

    // 4) wait for the zero-stores to complete, then cross-proxy fence
    if (tid == 0) {
        asm volatile("cp.async.bulk.wait_group 0;" ::: "memory");
        asm volatile("fence.proxy.async;" ::: "memory");
    }
    __syncthreads();   // all threads see chunk zeroed + s_mask valid

    // 5) fixup confined to this block's chunk: b fixed, d in [d0, d0+4)
    const int b  = bid >> 8;                 // bid*8192 floats -> b = bid/256
    const int d0 = (bid & 255) << 2;
    float* chunk_base = out + ((size_t)b * D_DIM + d0) * L_DIM;  // == gdst

    #pragma unroll
    for (int rep = 0; rep < 2; rep++) {
        int g = rep * TPB + tid;             // l4 group 0..511
        if ((s_mask[g >> 5] >> (g & 31)) & 1u) {    // ~13 threads total enter
            int l0 = g << 2;
            #pragma unroll
            for (int i = 0; i < 4; i++) {
                int l = l0 + i;
                int t = __ldg(x + l * B_DIM + b);   // L2-hot (x = 128KB)
                if (t < MAXTOK) {
                    float4 wv = *(const float4*)(w + (size_t)t * D_DIM + d0);
                    chunk_base[0 * L_DIM + l] = wv.x * SCALE;
                    chunk_base[1 * L_DIM + l] = wv.y * SCALE;
                    chunk_base[2 * L_DIM + l] = wv.z * SCALE;
                    chunk_base[3 * L_DIM + l] = wv.w * SCALE;
                }
            }
        }
    }
}

// ---------------------------------------------------------------------------
extern "C" void kernel_launch(void* const* d_in, const int* in_sizes, int n_in,
                              void* d_out, int out_size)
{
    const int*   x = (const int*)d_in[0];
    const float* w = (const float*)d_in[1];

    mask_kernel<<<16, 32>>>(x);
    tma_fill_kernel<<<NBLK, TPB>>>(x, w, (float*)d_out);
}